// round 15
// baseline (speedup 1.0000x reference)
#include <cuda_runtime.h>
#include <cuda_bf16.h>
#include <math.h>
#include <stdint.h>

// ---------------------------------------------------------------------------
// Problem constants
// ---------------------------------------------------------------------------
#define Bv      2
#define Cc      3
#define FRAMES  16
#define HWv     96
#define PT      4
#define PH      8
#define PW      8
#define GT      4
#define GH      12
#define GW      12
#define NPATCH  576
#define NTOK    128
#define Sv      704
#define SP      768
#define WIDTH   512
#define HEADS   8
#define LAYERS  8
#define MLPD    2048
#define HD      64
#define TOKSZ   5
#define EPSv    1e-6f
#define THETA   10000.0f

#define M_ROWS  (Bv*Sv)          // 1408
#define PATCH_F (Cc*PT*PH*PW)    // 768
#define P_ROWS  (Bv*NPATCH)      // 1152
#define BH      (Bv*HEADS)       // 16

// ---------------------------------------------------------------------------
// Scratch offsets (floats)
// ---------------------------------------------------------------------------
#define OFF_PATCH 0u
#define OFF_X     884736u
#define OFF_H     1605632u
#define OFF_QKV   2326528u
#define OFF_Q     4489216u      // [BH][SP][HD]
#define OFF_K     5275648u      // [BH][SP][HD]
#define OFF_V     6062080u      // Vt: [BH][HD][SP]
#define OFF_ATT   16285696u
#define OFF_MLP   17006592u
#define OFF_COS   19890176u
#define OFF_SIN   19912704u
#define SCRATCH_FLOATS 19935232u

__device__ float g_scratch[SCRATCH_FLOATS];

// ---------------------------------------------------------------------------
// TF32 helpers
// ---------------------------------------------------------------------------
__device__ __forceinline__ uint32_t f2tf(float x) {
    uint32_t r;
    asm("cvt.rna.tf32.f32 %0, %1;" : "=r"(r) : "f"(x));
    return r;
}
__device__ __forceinline__ float tfr(float x) { return __uint_as_float(f2tf(x)); }

__device__ __forceinline__ void mma_tf32(float (&d)[4], const uint32_t (&a)[4],
                                         const uint32_t (&b)[2]) {
    asm volatile(
        "mma.sync.aligned.m16n8k8.row.col.f32.tf32.tf32.f32 "
        "{%0,%1,%2,%3}, {%4,%5,%6,%7}, {%8,%9}, {%0,%1,%2,%3};\n"
        : "+f"(d[0]), "+f"(d[1]), "+f"(d[2]), "+f"(d[3])
        : "r"(a[0]), "r"(a[1]), "r"(a[2]), "r"(a[3]), "r"(b[0]), "r"(b[1]));
}

__device__ __forceinline__ void cp16(void* s, const void* g) {
    uint32_t sa = (uint32_t)__cvta_generic_to_shared(s);
    asm volatile("cp.async.cg.shared.global [%0], [%1], 16;\n" :: "r"(sa), "l"(g));
}

// ---------------------------------------------------------------------------
// Patchify (tf32-rounded output: GEMM A operand)
// ---------------------------------------------------------------------------
__global__ void patchify_kernel(const float* __restrict__ videos, float* __restrict__ patch) {
    int idx = blockIdx.x * blockDim.x + threadIdx.x;
    if (idx >= Bv * NPATCH * PATCH_F) return;
    int f = idx % PATCH_F;
    int p = (idx / PATCH_F) % NPATCH;
    int b = idx / (PATCH_F * NPATCH);
    int c  = f / (PT*PH*PW);
    int r  = f % (PT*PH*PW);
    int pt = r / (PH*PW);
    int ph = (r / PW) % PH;
    int pw = r % PW;
    int gt = p / (GH*GW);
    int gh = (p / GW) % GH;
    int gw = p % GW;
    int fr = gt*PT + pt;
    int y  = gh*PH + ph;
    int x  = gw*PW + pw;
    patch[idx] = tfr(videos[(((size_t)(b*Cc + c)*FRAMES + fr)*HWv + y)*HWv + x]);
}

// ---------------------------------------------------------------------------
// RoPE cos/sin table [S][32]
// ---------------------------------------------------------------------------
__global__ void rope_cs_kernel(float* __restrict__ cosb, float* __restrict__ sinb) {
    int s = blockIdx.x;
    int j = threadIdx.x;
    float pt = 0.f, ph = 0.f, pw = 0.f;
    if (s >= NTOK) {
        int p = s - NTOK;
        pt = (float)(p / (GH*GW));
        ph = (float)((p / GW) % GH);
        pw = (float)(p % GW);
    }
    float ang;
    if (j < 12)      ang = pt * powf(THETA, -(float)j / 12.f);
    else if (j < 22) ang = ph * powf(THETA, -(float)(j - 12) / 10.f);
    else             ang = pw * powf(THETA, -(float)(j - 22) / 10.f);
    cosb[s*32 + j] = cosf(ang);
    sinb[s*32 + j] = sinf(ang);
}

// ---------------------------------------------------------------------------
// TF32 MMA GEMM, 3-stage cp.async pipeline (dynamic smem), 128 threads.
// BM=128: 4 warps, 64x64 warp tile (MT=4, NT=8).
// BM=64 : 4 warps, 32x32 warp tile (MT=2, NT=4).
// W operand may be RAW fp32 (hardware truncates to tf32 in the MMA).
//   C[M,N] = A[M,K] @ W[N,K]^T (+ epilogue)
// EPI: 0 +bias | 1 +bias+residual | 2 +bias+GELU (round store)
// dynamic smem: 3*(BM+BN)*20*4 bytes
// ---------------------------------------------------------------------------
template<int BM, int BN, int EPI>
__global__ void mma_gemm(const float* __restrict__ A, const float* __restrict__ W,
                         const float* __restrict__ bias, const float* __restrict__ R,
                         float* __restrict__ C, int M, int N, int K) {
    constexpr int THREADS = 128;
    constexpr int WM = BM / 2;
    constexpr int WN = BN / 2;
    constexpr int MT = WM / 16;
    constexpr int NT = WN / 8;
    extern __shared__ uint32_t gsm[];
    uint32_t* As = gsm;                 // [3][BM*20]
    uint32_t* Ws = gsm + 3*BM*20;       // [3][BN*20]

    const float* Ag = A + (long)blockIdx.y * BM * K;
    const float* Wg = W + (long)blockIdx.x * BN * K;

    const int tid  = threadIdx.x;
    const int wid  = tid >> 5, lane = tid & 31;
    const int wm   = (wid >> 1) * WM;
    const int wn   = (wid & 1) * WN;
    const int g    = lane >> 2, tig = lane & 3;

    float acc[MT][NT][4];
    #pragma unroll
    for (int i = 0; i < MT; i++)
        #pragma unroll
        for (int j = 0; j < NT; j++)
            #pragma unroll
            for (int c = 0; c < 4; c++) acc[i][j][c] = 0.f;

    auto load_stage = [&](int buf, int k0) {
        #pragma unroll
        for (int i = 0; i < (BM*4)/THREADS; i++) {
            int e = tid + i * THREADS;
            int r = e >> 2, q = (e & 3) << 2;
            cp16(&As[buf*BM*20 + r*20 + q], Ag + (long)r * K + k0 + q);
        }
        #pragma unroll
        for (int i = 0; i < (BN*4)/THREADS; i++) {
            int e = tid + i * THREADS;
            int r = e >> 2, q = (e & 3) << 2;
            cp16(&Ws[buf*BN*20 + r*20 + q], Wg + (long)r * K + k0 + q);
        }
        asm volatile("cp.async.commit_group;\n");
    };

    const int KT = K >> 4;
    load_stage(0, 0);
    if (KT > 1) load_stage(1, 16);

    int buf = 0;
    for (int kt = 0; kt < KT; kt++) {
        if (kt + 1 < KT) asm volatile("cp.async.wait_group 1;\n");
        else             asm volatile("cp.async.wait_group 0;\n");
        __syncthreads();
        if (kt + 2 < KT) {
            int nb = buf + 2; if (nb >= 3) nb -= 3;
            load_stage(nb, (kt + 2) << 4);
        }

        const uint32_t* Ab = As + buf*BM*20;
        const uint32_t* Wb = Ws + buf*BN*20;
        #pragma unroll
        for (int ks = 0; ks < 2; ks++) {
            uint32_t af[MT][4], bf[NT][2];
            #pragma unroll
            for (int mt = 0; mt < MT; mt++) {
                int base = (wm + mt*16 + g) * 20 + ks*8 + tig;
                af[mt][0] = Ab[base];
                af[mt][1] = Ab[base + 160];   // row g+8
                af[mt][2] = Ab[base + 4];
                af[mt][3] = Ab[base + 164];
            }
            #pragma unroll
            for (int nt = 0; nt < NT; nt++) {
                int base = (wn + nt*8 + g) * 20 + ks*8 + tig;
                bf[nt][0] = Wb[base];
                bf[nt][1] = Wb[base + 4];
            }
            #pragma unroll
            for (int mt = 0; mt < MT; mt++)
                #pragma unroll
                for (int nt = 0; nt < NT; nt++)
                    mma_tf32(acc[mt][nt], af[mt], bf[nt]);
        }
        if (++buf == 3) buf = 0;
    }

    #pragma unroll
    for (int mt = 0; mt < MT; mt++) {
        #pragma unroll
        for (int nt = 0; nt < NT; nt++) {
            int row = blockIdx.y * BM + wm + mt*16 + g;
            int col = blockIdx.x * BN + wn + nt*8 + tig*2;
            float v0 = acc[mt][nt][0], v1 = acc[mt][nt][1];
            float v2 = acc[mt][nt][2], v3 = acc[mt][nt][3];
            float b0 = bias[col], b1 = bias[col+1];
            v0 += b0; v1 += b1; v2 += b0; v3 += b1;
            if (EPI == 1) {
                const float* Rp = R + (long)row * N + col;
                v0 += Rp[0]; v1 += Rp[1];
                v2 += Rp[(long)8*N]; v3 += Rp[(long)8*N + 1];
            }
            if (EPI == 2) {
                v0 = 0.5f*v0*(1.f + erff(v0*0.70710678118654752f));
                v1 = 0.5f*v1*(1.f + erff(v1*0.70710678118654752f));
                v2 = 0.5f*v2*(1.f + erff(v2*0.70710678118654752f));
                v3 = 0.5f*v3*(1.f + erff(v3*0.70710678118654752f));
                v0 = tfr(v0); v1 = tfr(v1); v2 = tfr(v2); v3 = tfr(v3);
            }
            *(float2*)(C + (long)row * N + col)       = make_float2(v0, v1);
            *(float2*)(C + (long)(row + 8) * N + col) = make_float2(v2, v3);
        }
    }
}

#define GEMM_SMEM_128 (3*(128+128)*20*4)   // 61440
#define GEMM_SMEM_64  (3*(64+64)*20*4)     // 30720

// ---------------------------------------------------------------------------
// Fused flash attention (tf32 MMA, online softmax).
// Q pre-scaled by 0.125 in rope_split (exact power of 2).
// Q fragments hoisted to registers (loaded once; Q smem is never rewritten).
// Grid (Sv/64, BH), 128 threads. smem 104448 B.
// ---------------------------------------------------------------------------
#define FQT 64
#define FKT 64
#define FTH 128
#define FROW 68
#define FTILE (64*FROW)
#define FLASH_SMEM ((FTILE*6) * 4)

__global__ void flash_kernel(const float* __restrict__ Q, const float* __restrict__ K,
                             const float* __restrict__ Vt, float* __restrict__ out) {
    extern __shared__ float fsm[];
    float* Qs = fsm;
    float* Ks = Qs + FTILE;
    float* Vs = Ks + 2*FTILE;
    float* Ps = Vs + 2*FTILE;

    const int bh = blockIdx.y;
    const int q0 = blockIdx.x * FQT;
    const int tid = threadIdx.x;
    const int wid = tid >> 5, lane = tid & 31;
    const int wm = wid * 16;
    const int g = lane >> 2, tig = lane & 3;

    const float* Qg = Q + ((size_t)bh * SP + q0) * HD;
    const float* Kg = K + (size_t)bh * SP * HD;
    const float* Vg = Vt + (size_t)bh * HD * SP;

    #pragma unroll
    for (int i = 0; i < 8; i++) {
        int e = tid + i * FTH;
        int r = e >> 4, c4 = (e & 15) << 2;
        cp16(&Qs[r*FROW + c4], Qg + (size_t)r*HD + c4);
    }
    auto load_kv = [&](int buf, int k0) {
        #pragma unroll
        for (int i = 0; i < 8; i++) {
            int e = tid + i * FTH;
            int r = e >> 4, c4 = (e & 15) << 2;
            cp16(&Ks[buf*FTILE + r*FROW + c4], Kg + (size_t)(k0 + r)*HD + c4);
        }
        #pragma unroll
        for (int i = 0; i < 8; i++) {
            int e = tid + i * FTH;
            int r = e >> 4, c4 = (e & 15) << 2;
            cp16(&Vs[buf*FTILE + r*FROW + c4], Vg + (size_t)r*SP + k0 + c4);
        }
        asm volatile("cp.async.commit_group;\n");
    };
    load_kv(0, 0);

    float m0 = -1e30f, m1 = -1e30f, l0 = 0.f, l1 = 0.f;
    float ao[8][4];
    #pragma unroll
    for (int nt = 0; nt < 8; nt++) { ao[nt][0]=0.f; ao[nt][1]=0.f; ao[nt][2]=0.f; ao[nt][3]=0.f; }

    uint32_t qf[8][4];          // Q fragments, loaded once after first tile

    const int NKT = Sv / FKT;   // 11
    for (int kt = 0; kt < NKT; kt++) {
        int buf = kt & 1;
        if (kt + 1 < NKT) {
            load_kv(buf ^ 1, (kt + 1) * FKT);
            asm volatile("cp.async.wait_group 1;\n");
        } else {
            asm volatile("cp.async.wait_group 0;\n");
        }
        __syncthreads();

        if (kt == 0) {
            const uint32_t* Qsu = (const uint32_t*)Qs;
            #pragma unroll
            for (int kc = 0; kc < 8; kc++) {
                qf[kc][0] = Qsu[(wm+g)*FROW + kc*8 + tig];
                qf[kc][1] = Qsu[(wm+g+8)*FROW + kc*8 + tig];
                qf[kc][2] = Qsu[(wm+g)*FROW + kc*8 + tig + 4];
                qf[kc][3] = Qsu[(wm+g+8)*FROW + kc*8 + tig + 4];
            }
        }

        float as[8][4];
        #pragma unroll
        for (int nt = 0; nt < 8; nt++) { as[nt][0]=0.f; as[nt][1]=0.f; as[nt][2]=0.f; as[nt][3]=0.f; }
        const uint32_t* Ksu = (const uint32_t*)(Ks + buf*FTILE);
        #pragma unroll
        for (int kc = 0; kc < 8; kc++) {
            #pragma unroll
            for (int nt = 0; nt < 8; nt++) {
                uint32_t b[2];
                b[0] = Ksu[(nt*8+g)*FROW + kc*8 + tig];
                b[1] = Ksu[(nt*8+g)*FROW + kc*8 + tig + 4];
                mma_tf32(as[nt], qf[kc], b);
            }
        }

        float mr0 = -1e30f, mr1 = -1e30f;
        #pragma unroll
        for (int nt = 0; nt < 8; nt++) {
            mr0 = fmaxf(mr0, fmaxf(as[nt][0], as[nt][1]));
            mr1 = fmaxf(mr1, fmaxf(as[nt][2], as[nt][3]));
        }
        mr0 = fmaxf(mr0, __shfl_xor_sync(0xffffffffu, mr0, 1));
        mr0 = fmaxf(mr0, __shfl_xor_sync(0xffffffffu, mr0, 2));
        mr1 = fmaxf(mr1, __shfl_xor_sync(0xffffffffu, mr1, 1));
        mr1 = fmaxf(mr1, __shfl_xor_sync(0xffffffffu, mr1, 2));
        float mn0 = fmaxf(m0, mr0), mn1 = fmaxf(m1, mr1);
        float c0 = __expf(m0 - mn0), c1 = __expf(m1 - mn1);
        m0 = mn0; m1 = mn1;

        float rs0 = 0.f, rs1 = 0.f;
        #pragma unroll
        for (int nt = 0; nt < 8; nt++) {
            float p0 = __expf(as[nt][0]-mn0), p1 = __expf(as[nt][1]-mn0);
            float p2 = __expf(as[nt][2]-mn1), p3 = __expf(as[nt][3]-mn1);
            rs0 += p0 + p1; rs1 += p2 + p3;
            int cbase = nt*8 + tig*2;
            Ps[(wm+g)*FROW + cbase]     = tfr(p0);
            Ps[(wm+g)*FROW + cbase + 1] = tfr(p1);
            Ps[(wm+g+8)*FROW + cbase]     = tfr(p2);
            Ps[(wm+g+8)*FROW + cbase + 1] = tfr(p3);
        }
        rs0 += __shfl_xor_sync(0xffffffffu, rs0, 1);
        rs0 += __shfl_xor_sync(0xffffffffu, rs0, 2);
        rs1 += __shfl_xor_sync(0xffffffffu, rs1, 1);
        rs1 += __shfl_xor_sync(0xffffffffu, rs1, 2);
        l0 = l0*c0 + rs0; l1 = l1*c1 + rs1;
        #pragma unroll
        for (int nt = 0; nt < 8; nt++) {
            ao[nt][0]*=c0; ao[nt][1]*=c0; ao[nt][2]*=c1; ao[nt][3]*=c1;
        }
        __syncwarp();

        const uint32_t* Psu = (const uint32_t*)Ps;
        const uint32_t* Vsu = (const uint32_t*)(Vs + buf*FTILE);
        #pragma unroll
        for (int kc = 0; kc < 8; kc++) {
            uint32_t a[4];
            a[0] = Psu[(wm+g)*FROW + kc*8 + tig];
            a[1] = Psu[(wm+g+8)*FROW + kc*8 + tig];
            a[2] = Psu[(wm+g)*FROW + kc*8 + tig + 4];
            a[3] = Psu[(wm+g+8)*FROW + kc*8 + tig + 4];
            #pragma unroll
            for (int nt = 0; nt < 8; nt++) {
                uint32_t b[2];
                b[0] = Vsu[(nt*8+g)*FROW + kc*8 + tig];
                b[1] = Vsu[(nt*8+g)*FROW + kc*8 + tig + 4];
                mma_tf32(ao[nt], a, b);
            }
        }
        __syncthreads();
    }

    float i0 = 1.0f / l0, i1 = 1.0f / l1;
    int b = bh >> 3, hh = bh & 7;
    int r0g = q0 + wm + g, r1g = r0g + 8;
    float* o0 = out + ((size_t)(b*Sv + r0g))*WIDTH + hh*HD;
    float* o1 = out + ((size_t)(b*Sv + r1g))*WIDTH + hh*HD;
    #pragma unroll
    for (int nt = 0; nt < 8; nt++) {
        int col = nt*8 + tig*2;
        *(float2*)(o0 + col) = make_float2(tfr(ao[nt][0]*i0), tfr(ao[nt][1]*i0));
        *(float2*)(o1 + col) = make_float2(tfr(ao[nt][2]*i1), tfr(ao[nt][3]*i1));
    }
}

// ---------------------------------------------------------------------------
// Block reduce (128 threads)
// ---------------------------------------------------------------------------
__device__ __forceinline__ float blk_sum128(float v, float* red) {
    #pragma unroll
    for (int o = 16; o; o >>= 1) v += __shfl_xor_sync(0xffffffffu, v, o);
    if ((threadIdx.x & 31) == 0) red[threadIdx.x >> 5] = v;
    __syncthreads();
    float s = red[0] + red[1] + red[2] + red[3];
    __syncthreads();
    return s;
}

// ---------------------------------------------------------------------------
// Build x
// ---------------------------------------------------------------------------
__global__ void build_x_kernel(const float* __restrict__ p, const float* __restrict__ mask,
                               const float* __restrict__ lt, const float* __restrict__ lp,
                               float* __restrict__ x) {
    __shared__ float red[4];
    int row = blockIdx.x;
    int b = row / Sv, s = row % Sv;
    float m = mask[0];
    float4* xr = (float4*)(x + (size_t)row * WIDTH);
    int t = threadIdx.x;
    if (s < NTOK) {
        float rs = rsqrtf(m*m + EPSv);
        float4 wv = ((const float4*)lt)[t];
        float4 o;
        o.x = m*rs*wv.x; o.y = m*rs*wv.y; o.z = m*rs*wv.z; o.w = m*rs*wv.w;
        xr[t] = o;
    } else {
        const float4* pr = (const float4*)(p + (size_t)(b*NPATCH + (s - NTOK)) * WIDTH);
        float4 v = pr[t];
        v.x += m; v.y += m; v.z += m; v.w += m;
        float ss = v.x*v.x + v.y*v.y + v.z*v.z + v.w*v.w;
        ss = blk_sum128(ss, red);
        float rs = rsqrtf(ss * (1.0f/WIDTH) + EPSv);
        float4 wv = ((const float4*)lp)[t];
        float4 o;
        o.x = v.x*rs*wv.x; o.y = v.y*rs*wv.y; o.z = v.z*rs*wv.z; o.w = v.w*rs*wv.w;
        xr[t] = o;
    }
}

// ---------------------------------------------------------------------------
// RMSNorm -> tf32-rounded output
// ---------------------------------------------------------------------------
__global__ void rmsnorm_kernel(const float* __restrict__ x, const float* __restrict__ w,
                               float* __restrict__ y) {
    __shared__ float red[4];
    int row = blockIdx.x;
    int t = threadIdx.x;
    float4 v = ((const float4*)(x + (size_t)row * WIDTH))[t];
    float ss = v.x*v.x + v.y*v.y + v.z*v.z + v.w*v.w;
    ss = blk_sum128(ss, red);
    float rs = rsqrtf(ss * (1.0f/WIDTH) + EPSv);
    float4 wv = ((const float4*)w)[t];
    float4 o;
    o.x = tfr(v.x*rs*wv.x); o.y = tfr(v.y*rs*wv.y);
    o.z = tfr(v.z*rs*wv.z); o.w = tfr(v.w*rs*wv.w);
    ((float4*)(y + (size_t)row * WIDTH))[t] = o;
}

// ---------------------------------------------------------------------------
// Split qkv + RoPE; tf32-rounded stores. Q scaled by 0.125 (exact).
// ---------------------------------------------------------------------------
__global__ void rope_split_kernel(const float* __restrict__ qkv,
                                  const float* __restrict__ cosb, const float* __restrict__ sinb,
                                  float* __restrict__ q, float* __restrict__ k,
                                  float* __restrict__ vt) {
    int bs = blockIdx.x;
    int b = bs / Sv, s = bs % Sv;
    const float* row = qkv + (size_t)bs * (3*WIDTH);
    int t = threadIdx.x;   // 256
    int h = t >> 5, j = t & 31;
    float c  = cosb[s*32 + j];
    float sn = sinb[s*32 + j];
    int bh = b*HEADS + h;
    size_t o = ((size_t)bh * SP + s) * HD;
    float q0 = row[h*HD + 2*j], q1 = row[h*HD + 2*j + 1];
    q[o + 2*j]     = tfr(q0*c - q1*sn) * 0.125f;
    q[o + 2*j + 1] = tfr(q0*sn + q1*c) * 0.125f;
    float k0 = row[WIDTH + h*HD + 2*j], k1 = row[WIDTH + h*HD + 2*j + 1];
    k[o + 2*j]     = tfr(k0*c - k1*sn);
    k[o + 2*j + 1] = tfr(k0*sn + k1*c);
    vt[((size_t)bh*HD + 2*j    )*SP + s] = tfr(row[2*WIDTH + h*HD + 2*j]);
    vt[((size_t)bh*HD + 2*j + 1)*SP + s] = tfr(row[2*WIDTH + h*HD + 2*j + 1]);
}

// ---------------------------------------------------------------------------
// Final token RMSNorm -> compact [256,512]
// ---------------------------------------------------------------------------
__global__ void final_norm_kernel(const float* __restrict__ x, const float* __restrict__ w,
                                  float* __restrict__ h) {
    __shared__ float red[4];
    int row = blockIdx.x;
    int b = row >> 7, t7 = row & 127;
    int tid = threadIdx.x;
    float4 v = ((const float4*)(x + ((size_t)(b*Sv + t7)) * WIDTH))[tid];
    float ss = v.x*v.x + v.y*v.y + v.z*v.z + v.w*v.w;
    ss = blk_sum128(ss, red);
    float rs = rsqrtf(ss * (1.0f/WIDTH) + EPSv);
    float4 wv = ((const float4*)w)[tid];
    float4 o;
    o.x = v.x*rs*wv.x; o.y = v.y*rs*wv.y; o.z = v.z*rs*wv.z; o.w = v.w*rs*wv.w;
    ((float4*)(h + (size_t)row * WIDTH))[tid] = o;
}

// ---------------------------------------------------------------------------
// proj_out
// ---------------------------------------------------------------------------
__global__ void proj_out_kernel(const float* __restrict__ h, const float* __restrict__ W,
                                const float* __restrict__ bias, float* __restrict__ out) {
    __shared__ float hs[WIDTH];
    int row = blockIdx.x;
    for (int e = threadIdx.x; e < WIDTH; e += 160) hs[e] = h[(size_t)row * WIDTH + e];
    __syncthreads();
    int warp = threadIdx.x >> 5, lane = threadIdx.x & 31;
    float d = 0.f;
    for (int e = lane; e < WIDTH; e += 32) d += hs[e] * W[warp*WIDTH + e];
    #pragma unroll
    for (int o = 16; o; o >>= 1) d += __shfl_xor_sync(0xffffffffu, d, o);
    if (lane == 0) out[row*TOKSZ + warp] = d + bias[warp];
}

// ---------------------------------------------------------------------------
// Launch
// ---------------------------------------------------------------------------
extern "C" void kernel_launch(void* const* d_in, const int* in_sizes, int n_in,
                              void* d_out, int out_size) {
    float* SC = nullptr;
    cudaGetSymbolAddress((void**)&SC, g_scratch);

    static bool attr_set = false;
    if (!attr_set) {
        cudaFuncSetAttribute(flash_kernel, cudaFuncAttributeMaxDynamicSharedMemorySize,
                             FLASH_SMEM);
        cudaFuncSetAttribute(mma_gemm<128,128,0>, cudaFuncAttributeMaxDynamicSharedMemorySize,
                             GEMM_SMEM_128);
        cudaFuncSetAttribute(mma_gemm<128,128,2>, cudaFuncAttributeMaxDynamicSharedMemorySize,
                             GEMM_SMEM_128);
        cudaFuncSetAttribute(mma_gemm<64,64,0>, cudaFuncAttributeMaxDynamicSharedMemorySize,
                             GEMM_SMEM_64);
        cudaFuncSetAttribute(mma_gemm<64,64,1>, cudaFuncAttributeMaxDynamicSharedMemorySize,
                             GEMM_SMEM_64);
        attr_set = true;
    }

    const float* videos     = (const float*)d_in[0];
    const float* mask_token = (const float*)d_in[2];
    const float* ln_pre_t_w = (const float*)d_in[3];
    const float* ln_pre_p_w = (const float*)d_in[4];
    const float* proj_in_w  = (const float*)d_in[5];
    const float* proj_in_b  = (const float*)d_in[6];
    const float* ln1_w      = (const float*)d_in[7];
    const float* qkv_w      = (const float*)d_in[8];
    const float* qkv_b      = (const float*)d_in[9];
    const float* attn_out_w = (const float*)d_in[10];
    const float* attn_out_b = (const float*)d_in[11];
    const float* ln2_w      = (const float*)d_in[12];
    const float* fc1_w      = (const float*)d_in[13];
    const float* fc1_b      = (const float*)d_in[14];
    const float* fc2_w      = (const float*)d_in[15];
    const float* fc2_b      = (const float*)d_in[16];
    const float* ln_post_w  = (const float*)d_in[17];
    const float* proj_out_w = (const float*)d_in[18];
    const float* proj_out_b = (const float*)d_in[19];
    float* out = (float*)d_out;

    float* patch = SC + OFF_PATCH;
    float* x     = SC + OFF_X;
    float* h     = SC + OFF_H;
    float* qkv   = SC + OFF_QKV;
    float* Qp    = SC + OFF_Q;
    float* Kp    = SC + OFF_K;
    float* Vt    = SC + OFF_V;
    float* att   = SC + OFF_ATT;
    float* mlp   = SC + OFF_MLP;
    float* cosb  = SC + OFF_COS;
    float* sinb  = SC + OFF_SIN;

    // Weights are fed RAW to the tf32 MMA (hardware truncation) — no tfround.
    patchify_kernel<<<(Bv*NPATCH*PATCH_F + 255)/256, 256>>>(videos, patch);
    rope_cs_kernel<<<Sv, 32>>>(cosb, sinb);
    mma_gemm<64,64,0><<<dim3(WIDTH/64, P_ROWS/64), 128, GEMM_SMEM_64>>>(
        patch, proj_in_w, proj_in_b, nullptr, h, P_ROWS, WIDTH, PATCH_F);
    build_x_kernel<<<M_ROWS, 128>>>(h, mask_token, ln_pre_t_w, ln_pre_p_w, x);

    for (int l = 0; l < LAYERS; l++) {
        const float* l1w  = ln1_w      + (size_t)l * WIDTH;
        const float* qw   = qkv_w      + (size_t)l * 3*WIDTH*WIDTH;
        const float* qb   = qkv_b      + (size_t)l * 3*WIDTH;
        const float* aow  = attn_out_w + (size_t)l * WIDTH*WIDTH;
        const float* aob  = attn_out_b + (size_t)l * WIDTH;
        const float* l2w  = ln2_w      + (size_t)l * WIDTH;
        const float* f1w  = fc1_w      + (size_t)l * MLPD*WIDTH;
        const float* f1b  = fc1_b      + (size_t)l * MLPD;
        const float* f2w  = fc2_w      + (size_t)l * WIDTH*MLPD;
        const float* f2b  = fc2_b      + (size_t)l * WIDTH;

        rmsnorm_kernel<<<M_ROWS, 128>>>(x, l1w, h);
        mma_gemm<128,128,0><<<dim3(3*WIDTH/128, M_ROWS/128), 128, GEMM_SMEM_128>>>(
            h, qw, qb, nullptr, qkv, M_ROWS, 3*WIDTH, WIDTH);
        rope_split_kernel<<<M_ROWS, 256>>>(qkv, cosb, sinb, Qp, Kp, Vt);
        flash_kernel<<<dim3(Sv/FQT, BH), FTH, FLASH_SMEM>>>(Qp, Kp, Vt, att);
        mma_gemm<64,64,1><<<dim3(WIDTH/64, M_ROWS/64), 128, GEMM_SMEM_64>>>(
            att, aow, aob, x, x, M_ROWS, WIDTH, WIDTH);
        rmsnorm_kernel<<<M_ROWS, 128>>>(x, l2w, h);
        mma_gemm<128,128,2><<<dim3(MLPD/128, M_ROWS/128), 128, GEMM_SMEM_128>>>(
            h, f1w, f1b, nullptr, mlp, M_ROWS, MLPD, WIDTH);
        mma_gemm<64,64,1><<<dim3(WIDTH/64, M_ROWS/64), 128, GEMM_SMEM_64>>>(
            mlp, f2w, f2b, x, x, M_ROWS, WIDTH, MLPD);
    }

    final_norm_kernel<<<Bv*NTOK, 128>>>(x, ln_post_w, h);
    proj_out_kernel<<<Bv*NTOK, 160>>>(h, proj_out_w, proj_out_b, out);
}

// round 17
// speedup vs baseline: 1.0159x; 1.0159x over previous
#include <cuda_runtime.h>
#include <cuda_bf16.h>
#include <math.h>
#include <stdint.h>

// ---------------------------------------------------------------------------
// Problem constants
// ---------------------------------------------------------------------------
#define Bv      2
#define Cc      3
#define FRAMES  16
#define HWv     96
#define PT      4
#define PH      8
#define PW      8
#define GT      4
#define GH      12
#define GW      12
#define NPATCH  576
#define NTOK    128
#define Sv      704
#define SP      768
#define WIDTH   512
#define HEADS   8
#define LAYERS  8
#define MLPD    2048
#define HD      64
#define TOKSZ   5
#define EPSv    1e-6f
#define THETA   10000.0f

#define M_ROWS  (Bv*Sv)          // 1408
#define PATCH_F (Cc*PT*PH*PW)    // 768
#define P_ROWS  (Bv*NPATCH)      // 1152
#define BH      (Bv*HEADS)       // 16

// ---------------------------------------------------------------------------
// Scratch offsets (floats)
// ---------------------------------------------------------------------------
#define OFF_PATCH 0u
#define OFF_X     884736u
#define OFF_H     1605632u
#define OFF_QKV   2326528u
#define OFF_Q     4489216u      // [BH][SP][HD]
#define OFF_K     5275648u      // [BH][SP][HD]
#define OFF_V     6062080u      // Vt: [BH][HD][SP]
#define OFF_ATT   16285696u
#define OFF_MLP   17006592u
#define OFF_COS   19890176u
#define OFF_SIN   19912704u
#define SCRATCH_FLOATS 19935232u

__device__ float g_scratch[SCRATCH_FLOATS];

// ---------------------------------------------------------------------------
// TF32 helpers
// ---------------------------------------------------------------------------
__device__ __forceinline__ uint32_t f2tf(float x) {
    uint32_t r;
    asm("cvt.rna.tf32.f32 %0, %1;" : "=r"(r) : "f"(x));
    return r;
}
__device__ __forceinline__ float tfr(float x) { return __uint_as_float(f2tf(x)); }

__device__ __forceinline__ void mma_tf32(float (&d)[4], const uint32_t (&a)[4],
                                         const uint32_t (&b)[2]) {
    asm volatile(
        "mma.sync.aligned.m16n8k8.row.col.f32.tf32.tf32.f32 "
        "{%0,%1,%2,%3}, {%4,%5,%6,%7}, {%8,%9}, {%0,%1,%2,%3};\n"
        : "+f"(d[0]), "+f"(d[1]), "+f"(d[2]), "+f"(d[3])
        : "r"(a[0]), "r"(a[1]), "r"(a[2]), "r"(a[3]), "r"(b[0]), "r"(b[1]));
}

__device__ __forceinline__ void cp16(void* s, const void* g) {
    uint32_t sa = (uint32_t)__cvta_generic_to_shared(s);
    asm volatile("cp.async.cg.shared.global [%0], [%1], 16;\n" :: "r"(sa), "l"(g));
}

// ---------------------------------------------------------------------------
// Patchify (tf32-rounded output: GEMM A operand)
// ---------------------------------------------------------------------------
__global__ void patchify_kernel(const float* __restrict__ videos, float* __restrict__ patch) {
    int idx = blockIdx.x * blockDim.x + threadIdx.x;
    if (idx >= Bv * NPATCH * PATCH_F) return;
    int f = idx % PATCH_F;
    int p = (idx / PATCH_F) % NPATCH;
    int b = idx / (PATCH_F * NPATCH);
    int c  = f / (PT*PH*PW);
    int r  = f % (PT*PH*PW);
    int pt = r / (PH*PW);
    int ph = (r / PW) % PH;
    int pw = r % PW;
    int gt = p / (GH*GW);
    int gh = (p / GW) % GH;
    int gw = p % GW;
    int fr = gt*PT + pt;
    int y  = gh*PH + ph;
    int x  = gw*PW + pw;
    patch[idx] = tfr(videos[(((size_t)(b*Cc + c)*FRAMES + fr)*HWv + y)*HWv + x]);
}

// ---------------------------------------------------------------------------
// RoPE cos/sin table [S][32]
// ---------------------------------------------------------------------------
__global__ void rope_cs_kernel(float* __restrict__ cosb, float* __restrict__ sinb) {
    int s = blockIdx.x;
    int j = threadIdx.x;
    float pt = 0.f, ph = 0.f, pw = 0.f;
    if (s >= NTOK) {
        int p = s - NTOK;
        pt = (float)(p / (GH*GW));
        ph = (float)((p / GW) % GH);
        pw = (float)(p % GW);
    }
    float ang;
    if (j < 12)      ang = pt * powf(THETA, -(float)j / 12.f);
    else if (j < 22) ang = ph * powf(THETA, -(float)(j - 12) / 10.f);
    else             ang = pw * powf(THETA, -(float)(j - 22) / 10.f);
    cosb[s*32 + j] = cosf(ang);
    sinb[s*32 + j] = sinf(ang);
}

// ---------------------------------------------------------------------------
// TF32 MMA GEMM, 3-stage cp.async pipeline (dynamic smem), 128 threads.
// BM=128: 4 warps, 64x64 warp tile (MT=4, NT=8).
// BM=64 : 4 warps, 32x32 warp tile (MT=2, NT=4).
// W operand may be RAW fp32 (hardware truncates to tf32 in the MMA).
//   C[M,N] = A[M,K] @ W[N,K]^T (+ epilogue)
// EPI: 0 +bias | 1 +bias+residual | 2 +bias+GELU (round store)
// dynamic smem: 3*(BM+BN)*20*4 bytes
// ---------------------------------------------------------------------------
template<int BM, int BN, int EPI>
__global__ void mma_gemm(const float* __restrict__ A, const float* __restrict__ W,
                         const float* __restrict__ bias, const float* __restrict__ R,
                         float* __restrict__ C, int M, int N, int K) {
    constexpr int THREADS = 128;
    constexpr int WM = BM / 2;
    constexpr int WN = BN / 2;
    constexpr int MT = WM / 16;
    constexpr int NT = WN / 8;
    extern __shared__ uint32_t gsm[];
    uint32_t* As = gsm;                 // [3][BM*20]
    uint32_t* Ws = gsm + 3*BM*20;       // [3][BN*20]

    const float* Ag = A + (long)blockIdx.y * BM * K;
    const float* Wg = W + (long)blockIdx.x * BN * K;

    const int tid  = threadIdx.x;
    const int wid  = tid >> 5, lane = tid & 31;
    const int wm   = (wid >> 1) * WM;
    const int wn   = (wid & 1) * WN;
    const int g    = lane >> 2, tig = lane & 3;

    float acc[MT][NT][4];
    #pragma unroll
    for (int i = 0; i < MT; i++)
        #pragma unroll
        for (int j = 0; j < NT; j++)
            #pragma unroll
            for (int c = 0; c < 4; c++) acc[i][j][c] = 0.f;

    auto load_stage = [&](int buf, int k0) {
        #pragma unroll
        for (int i = 0; i < (BM*4)/THREADS; i++) {
            int e = tid + i * THREADS;
            int r = e >> 2, q = (e & 3) << 2;
            cp16(&As[buf*BM*20 + r*20 + q], Ag + (long)r * K + k0 + q);
        }
        #pragma unroll
        for (int i = 0; i < (BN*4)/THREADS; i++) {
            int e = tid + i * THREADS;
            int r = e >> 2, q = (e & 3) << 2;
            cp16(&Ws[buf*BN*20 + r*20 + q], Wg + (long)r * K + k0 + q);
        }
        asm volatile("cp.async.commit_group;\n");
    };

    const int KT = K >> 4;
    load_stage(0, 0);
    if (KT > 1) load_stage(1, 16);

    int buf = 0;
    for (int kt = 0; kt < KT; kt++) {
        if (kt + 1 < KT) asm volatile("cp.async.wait_group 1;\n");
        else             asm volatile("cp.async.wait_group 0;\n");
        __syncthreads();
        if (kt + 2 < KT) {
            int nb = buf + 2; if (nb >= 3) nb -= 3;
            load_stage(nb, (kt + 2) << 4);
        }

        const uint32_t* Ab = As + buf*BM*20;
        const uint32_t* Wb = Ws + buf*BN*20;
        #pragma unroll
        for (int ks = 0; ks < 2; ks++) {
            uint32_t af[MT][4], bf[NT][2];
            #pragma unroll
            for (int mt = 0; mt < MT; mt++) {
                int base = (wm + mt*16 + g) * 20 + ks*8 + tig;
                af[mt][0] = Ab[base];
                af[mt][1] = Ab[base + 160];   // row g+8
                af[mt][2] = Ab[base + 4];
                af[mt][3] = Ab[base + 164];
            }
            #pragma unroll
            for (int nt = 0; nt < NT; nt++) {
                int base = (wn + nt*8 + g) * 20 + ks*8 + tig;
                bf[nt][0] = Wb[base];
                bf[nt][1] = Wb[base + 4];
            }
            #pragma unroll
            for (int mt = 0; mt < MT; mt++)
                #pragma unroll
                for (int nt = 0; nt < NT; nt++)
                    mma_tf32(acc[mt][nt], af[mt], bf[nt]);
        }
        if (++buf == 3) buf = 0;
    }

    #pragma unroll
    for (int mt = 0; mt < MT; mt++) {
        #pragma unroll
        for (int nt = 0; nt < NT; nt++) {
            int row = blockIdx.y * BM + wm + mt*16 + g;
            int col = blockIdx.x * BN + wn + nt*8 + tig*2;
            float v0 = acc[mt][nt][0], v1 = acc[mt][nt][1];
            float v2 = acc[mt][nt][2], v3 = acc[mt][nt][3];
            float b0 = bias[col], b1 = bias[col+1];
            v0 += b0; v1 += b1; v2 += b0; v3 += b1;
            if (EPI == 1) {
                const float* Rp = R + (long)row * N + col;
                v0 += Rp[0]; v1 += Rp[1];
                v2 += Rp[(long)8*N]; v3 += Rp[(long)8*N + 1];
            }
            if (EPI == 2) {
                v0 = 0.5f*v0*(1.f + erff(v0*0.70710678118654752f));
                v1 = 0.5f*v1*(1.f + erff(v1*0.70710678118654752f));
                v2 = 0.5f*v2*(1.f + erff(v2*0.70710678118654752f));
                v3 = 0.5f*v3*(1.f + erff(v3*0.70710678118654752f));
                v0 = tfr(v0); v1 = tfr(v1); v2 = tfr(v2); v3 = tfr(v3);
            }
            *(float2*)(C + (long)row * N + col)       = make_float2(v0, v1);
            *(float2*)(C + (long)(row + 8) * N + col) = make_float2(v2, v3);
        }
    }
}

#define GEMM_SMEM_128 (3*(128+128)*20*4)   // 61440
#define GEMM_SMEM_64  (3*(64+64)*20*4)     // 30720

// ---------------------------------------------------------------------------
// Fused flash attention (tf32 MMA, online softmax).
// Q pre-scaled by 0.125 in rope_split (exact power of 2).
// Grid (Sv/64, BH), 128 threads. smem 104448 B.
// ---------------------------------------------------------------------------
#define FQT 64
#define FKT 64
#define FTH 128
#define FROW 68
#define FTILE (64*FROW)
#define FLASH_SMEM ((FTILE*6) * 4)

__global__ void flash_kernel(const float* __restrict__ Q, const float* __restrict__ K,
                             const float* __restrict__ Vt, float* __restrict__ out) {
    extern __shared__ float fsm[];
    float* Qs = fsm;
    float* Ks = Qs + FTILE;
    float* Vs = Ks + 2*FTILE;
    float* Ps = Vs + 2*FTILE;

    const int bh = blockIdx.y;
    const int q0 = blockIdx.x * FQT;
    const int tid = threadIdx.x;
    const int wid = tid >> 5, lane = tid & 31;
    const int wm = wid * 16;
    const int g = lane >> 2, tig = lane & 3;

    const float* Qg = Q + ((size_t)bh * SP + q0) * HD;
    const float* Kg = K + (size_t)bh * SP * HD;
    const float* Vg = Vt + (size_t)bh * HD * SP;

    #pragma unroll
    for (int i = 0; i < 8; i++) {
        int e = tid + i * FTH;
        int r = e >> 4, c4 = (e & 15) << 2;
        cp16(&Qs[r*FROW + c4], Qg + (size_t)r*HD + c4);
    }
    auto load_kv = [&](int buf, int k0) {
        #pragma unroll
        for (int i = 0; i < 8; i++) {
            int e = tid + i * FTH;
            int r = e >> 4, c4 = (e & 15) << 2;
            cp16(&Ks[buf*FTILE + r*FROW + c4], Kg + (size_t)(k0 + r)*HD + c4);
        }
        #pragma unroll
        for (int i = 0; i < 8; i++) {
            int e = tid + i * FTH;
            int r = e >> 4, c4 = (e & 15) << 2;
            cp16(&Vs[buf*FTILE + r*FROW + c4], Vg + (size_t)r*SP + k0 + c4);
        }
        asm volatile("cp.async.commit_group;\n");
    };
    load_kv(0, 0);

    float m0 = -1e30f, m1 = -1e30f, l0 = 0.f, l1 = 0.f;
    float ao[8][4];
    #pragma unroll
    for (int nt = 0; nt < 8; nt++) { ao[nt][0]=0.f; ao[nt][1]=0.f; ao[nt][2]=0.f; ao[nt][3]=0.f; }

    const int NKT = Sv / FKT;   // 11
    for (int kt = 0; kt < NKT; kt++) {
        int buf = kt & 1;
        if (kt + 1 < NKT) {
            load_kv(buf ^ 1, (kt + 1) * FKT);
            asm volatile("cp.async.wait_group 1;\n");
        } else {
            asm volatile("cp.async.wait_group 0;\n");
        }
        __syncthreads();

        float as[8][4];
        #pragma unroll
        for (int nt = 0; nt < 8; nt++) { as[nt][0]=0.f; as[nt][1]=0.f; as[nt][2]=0.f; as[nt][3]=0.f; }
        const uint32_t* Qsu = (const uint32_t*)Qs;
        const uint32_t* Ksu = (const uint32_t*)(Ks + buf*FTILE);
        #pragma unroll
        for (int kc = 0; kc < 8; kc++) {
            uint32_t a[4];
            a[0] = Qsu[(wm+g)*FROW + kc*8 + tig];
            a[1] = Qsu[(wm+g+8)*FROW + kc*8 + tig];
            a[2] = Qsu[(wm+g)*FROW + kc*8 + tig + 4];
            a[3] = Qsu[(wm+g+8)*FROW + kc*8 + tig + 4];
            #pragma unroll
            for (int nt = 0; nt < 8; nt++) {
                uint32_t b[2];
                b[0] = Ksu[(nt*8+g)*FROW + kc*8 + tig];
                b[1] = Ksu[(nt*8+g)*FROW + kc*8 + tig + 4];
                mma_tf32(as[nt], a, b);
            }
        }

        float mr0 = -1e30f, mr1 = -1e30f;
        #pragma unroll
        for (int nt = 0; nt < 8; nt++) {
            mr0 = fmaxf(mr0, fmaxf(as[nt][0], as[nt][1]));
            mr1 = fmaxf(mr1, fmaxf(as[nt][2], as[nt][3]));
        }
        mr0 = fmaxf(mr0, __shfl_xor_sync(0xffffffffu, mr0, 1));
        mr0 = fmaxf(mr0, __shfl_xor_sync(0xffffffffu, mr0, 2));
        mr1 = fmaxf(mr1, __shfl_xor_sync(0xffffffffu, mr1, 1));
        mr1 = fmaxf(mr1, __shfl_xor_sync(0xffffffffu, mr1, 2));
        float mn0 = fmaxf(m0, mr0), mn1 = fmaxf(m1, mr1);
        float c0 = __expf(m0 - mn0), c1 = __expf(m1 - mn1);
        m0 = mn0; m1 = mn1;

        float rs0 = 0.f, rs1 = 0.f;
        #pragma unroll
        for (int nt = 0; nt < 8; nt++) {
            float p0 = __expf(as[nt][0]-mn0), p1 = __expf(as[nt][1]-mn0);
            float p2 = __expf(as[nt][2]-mn1), p3 = __expf(as[nt][3]-mn1);
            rs0 += p0 + p1; rs1 += p2 + p3;
            int cbase = nt*8 + tig*2;
            Ps[(wm+g)*FROW + cbase]     = tfr(p0);
            Ps[(wm+g)*FROW + cbase + 1] = tfr(p1);
            Ps[(wm+g+8)*FROW + cbase]     = tfr(p2);
            Ps[(wm+g+8)*FROW + cbase + 1] = tfr(p3);
        }
        rs0 += __shfl_xor_sync(0xffffffffu, rs0, 1);
        rs0 += __shfl_xor_sync(0xffffffffu, rs0, 2);
        rs1 += __shfl_xor_sync(0xffffffffu, rs1, 1);
        rs1 += __shfl_xor_sync(0xffffffffu, rs1, 2);
        l0 = l0*c0 + rs0; l1 = l1*c1 + rs1;
        #pragma unroll
        for (int nt = 0; nt < 8; nt++) {
            ao[nt][0]*=c0; ao[nt][1]*=c0; ao[nt][2]*=c1; ao[nt][3]*=c1;
        }
        __syncwarp();

        const uint32_t* Psu = (const uint32_t*)Ps;
        const uint32_t* Vsu = (const uint32_t*)(Vs + buf*FTILE);
        #pragma unroll
        for (int kc = 0; kc < 8; kc++) {
            uint32_t a[4];
            a[0] = Psu[(wm+g)*FROW + kc*8 + tig];
            a[1] = Psu[(wm+g+8)*FROW + kc*8 + tig];
            a[2] = Psu[(wm+g)*FROW + kc*8 + tig + 4];
            a[3] = Psu[(wm+g+8)*FROW + kc*8 + tig + 4];
            #pragma unroll
            for (int nt = 0; nt < 8; nt++) {
                uint32_t b[2];
                b[0] = Vsu[(nt*8+g)*FROW + kc*8 + tig];
                b[1] = Vsu[(nt*8+g)*FROW + kc*8 + tig + 4];
                mma_tf32(ao[nt], a, b);
            }
        }
        __syncthreads();
    }

    float i0 = 1.0f / l0, i1 = 1.0f / l1;
    int b = bh >> 3, hh = bh & 7;
    int r0g = q0 + wm + g, r1g = r0g + 8;
    float* o0 = out + ((size_t)(b*Sv + r0g))*WIDTH + hh*HD;
    float* o1 = out + ((size_t)(b*Sv + r1g))*WIDTH + hh*HD;
    #pragma unroll
    for (int nt = 0; nt < 8; nt++) {
        int col = nt*8 + tig*2;
        *(float2*)(o0 + col) = make_float2(tfr(ao[nt][0]*i0), tfr(ao[nt][1]*i0));
        *(float2*)(o1 + col) = make_float2(tfr(ao[nt][2]*i1), tfr(ao[nt][3]*i1));
    }
}

// ---------------------------------------------------------------------------
// Block reduce (128 threads)
// ---------------------------------------------------------------------------
__device__ __forceinline__ float blk_sum128(float v, float* red) {
    #pragma unroll
    for (int o = 16; o; o >>= 1) v += __shfl_xor_sync(0xffffffffu, v, o);
    if ((threadIdx.x & 31) == 0) red[threadIdx.x >> 5] = v;
    __syncthreads();
    float s = red[0] + red[1] + red[2] + red[3];
    __syncthreads();
    return s;
}

// ---------------------------------------------------------------------------
// Build x
// ---------------------------------------------------------------------------
__global__ void build_x_kernel(const float* __restrict__ p, const float* __restrict__ mask,
                               const float* __restrict__ lt, const float* __restrict__ lp,
                               float* __restrict__ x) {
    __shared__ float red[4];
    int row = blockIdx.x;
    int b = row / Sv, s = row % Sv;
    float m = mask[0];
    float4* xr = (float4*)(x + (size_t)row * WIDTH);
    int t = threadIdx.x;
    if (s < NTOK) {
        float rs = rsqrtf(m*m + EPSv);
        float4 wv = ((const float4*)lt)[t];
        float4 o;
        o.x = m*rs*wv.x; o.y = m*rs*wv.y; o.z = m*rs*wv.z; o.w = m*rs*wv.w;
        xr[t] = o;
    } else {
        const float4* pr = (const float4*)(p + (size_t)(b*NPATCH + (s - NTOK)) * WIDTH);
        float4 v = pr[t];
        v.x += m; v.y += m; v.z += m; v.w += m;
        float ss = v.x*v.x + v.y*v.y + v.z*v.z + v.w*v.w;
        ss = blk_sum128(ss, red);
        float rs = rsqrtf(ss * (1.0f/WIDTH) + EPSv);
        float4 wv = ((const float4*)lp)[t];
        float4 o;
        o.x = v.x*rs*wv.x; o.y = v.y*rs*wv.y; o.z = v.z*rs*wv.z; o.w = v.w*rs*wv.w;
        xr[t] = o;
    }
}

// ---------------------------------------------------------------------------
// RMSNorm -> tf32-rounded output
// ---------------------------------------------------------------------------
__global__ void rmsnorm_kernel(const float* __restrict__ x, const float* __restrict__ w,
                               float* __restrict__ y) {
    __shared__ float red[4];
    int row = blockIdx.x;
    int t = threadIdx.x;
    float4 v = ((const float4*)(x + (size_t)row * WIDTH))[t];
    float ss = v.x*v.x + v.y*v.y + v.z*v.z + v.w*v.w;
    ss = blk_sum128(ss, red);
    float rs = rsqrtf(ss * (1.0f/WIDTH) + EPSv);
    float4 wv = ((const float4*)w)[t];
    float4 o;
    o.x = tfr(v.x*rs*wv.x); o.y = tfr(v.y*rs*wv.y);
    o.z = tfr(v.z*rs*wv.z); o.w = tfr(v.w*rs*wv.w);
    ((float4*)(y + (size_t)row * WIDTH))[t] = o;
}

// ---------------------------------------------------------------------------
// Split qkv + RoPE; float2 vectorized; tf32-rounded stores.
// Q scaled by 0.125 (exact).
// ---------------------------------------------------------------------------
__global__ void rope_split_kernel(const float* __restrict__ qkv,
                                  const float* __restrict__ cosb, const float* __restrict__ sinb,
                                  float* __restrict__ q, float* __restrict__ k,
                                  float* __restrict__ vt) {
    int bs = blockIdx.x;
    int b = bs / Sv, s = bs % Sv;
    const float* row = qkv + (size_t)bs * (3*WIDTH);
    int t = threadIdx.x;   // 256
    int h = t >> 5, j = t & 31;
    float c  = cosb[s*32 + j];
    float sn = sinb[s*32 + j];
    int bh = b*HEADS + h;
    size_t o = ((size_t)bh * SP + s) * HD;

    float2 qv = *(const float2*)(row + h*HD + 2*j);
    float2 kv = *(const float2*)(row + WIDTH + h*HD + 2*j);
    float2 vv = *(const float2*)(row + 2*WIDTH + h*HD + 2*j);

    float2 qo, ko;
    qo.x = tfr(qv.x*c - qv.y*sn) * 0.125f;
    qo.y = tfr(qv.x*sn + qv.y*c) * 0.125f;
    ko.x = tfr(kv.x*c - kv.y*sn);
    ko.y = tfr(kv.x*sn + kv.y*c);
    *(float2*)(q + o + 2*j) = qo;
    *(float2*)(k + o + 2*j) = ko;
    vt[((size_t)bh*HD + 2*j    )*SP + s] = tfr(vv.x);
    vt[((size_t)bh*HD + 2*j + 1)*SP + s] = tfr(vv.y);
}

// ---------------------------------------------------------------------------
// Final token RMSNorm -> compact [256,512]
// ---------------------------------------------------------------------------
__global__ void final_norm_kernel(const float* __restrict__ x, const float* __restrict__ w,
                                  float* __restrict__ h) {
    __shared__ float red[4];
    int row = blockIdx.x;
    int b = row >> 7, t7 = row & 127;
    int tid = threadIdx.x;
    float4 v = ((const float4*)(x + ((size_t)(b*Sv + t7)) * WIDTH))[tid];
    float ss = v.x*v.x + v.y*v.y + v.z*v.z + v.w*v.w;
    ss = blk_sum128(ss, red);
    float rs = rsqrtf(ss * (1.0f/WIDTH) + EPSv);
    float4 wv = ((const float4*)w)[tid];
    float4 o;
    o.x = v.x*rs*wv.x; o.y = v.y*rs*wv.y; o.z = v.z*rs*wv.z; o.w = v.w*rs*wv.w;
    ((float4*)(h + (size_t)row * WIDTH))[tid] = o;
}

// ---------------------------------------------------------------------------
// proj_out
// ---------------------------------------------------------------------------
__global__ void proj_out_kernel(const float* __restrict__ h, const float* __restrict__ W,
                                const float* __restrict__ bias, float* __restrict__ out) {
    __shared__ float hs[WIDTH];
    int row = blockIdx.x;
    for (int e = threadIdx.x; e < WIDTH; e += 160) hs[e] = h[(size_t)row * WIDTH + e];
    __syncthreads();
    int warp = threadIdx.x >> 5, lane = threadIdx.x & 31;
    float d = 0.f;
    for (int e = lane; e < WIDTH; e += 32) d += hs[e] * W[warp*WIDTH + e];
    #pragma unroll
    for (int o = 16; o; o >>= 1) d += __shfl_xor_sync(0xffffffffu, d, o);
    if (lane == 0) out[row*TOKSZ + warp] = d + bias[warp];
}

// ---------------------------------------------------------------------------
// Launch
// ---------------------------------------------------------------------------
extern "C" void kernel_launch(void* const* d_in, const int* in_sizes, int n_in,
                              void* d_out, int out_size) {
    float* SC = nullptr;
    cudaGetSymbolAddress((void**)&SC, g_scratch);

    static bool attr_set = false;
    if (!attr_set) {
        cudaFuncSetAttribute(flash_kernel, cudaFuncAttributeMaxDynamicSharedMemorySize,
                             FLASH_SMEM);
        cudaFuncSetAttribute(mma_gemm<128,128,0>, cudaFuncAttributeMaxDynamicSharedMemorySize,
                             GEMM_SMEM_128);
        cudaFuncSetAttribute(mma_gemm<128,128,2>, cudaFuncAttributeMaxDynamicSharedMemorySize,
                             GEMM_SMEM_128);
        cudaFuncSetAttribute(mma_gemm<64,64,0>, cudaFuncAttributeMaxDynamicSharedMemorySize,
                             GEMM_SMEM_64);
        cudaFuncSetAttribute(mma_gemm<64,64,1>, cudaFuncAttributeMaxDynamicSharedMemorySize,
                             GEMM_SMEM_64);
        attr_set = true;
    }

    const float* videos     = (const float*)d_in[0];
    const float* mask_token = (const float*)d_in[2];
    const float* ln_pre_t_w = (const float*)d_in[3];
    const float* ln_pre_p_w = (const float*)d_in[4];
    const float* proj_in_w  = (const float*)d_in[5];
    const float* proj_in_b  = (const float*)d_in[6];
    const float* ln1_w      = (const float*)d_in[7];
    const float* qkv_w      = (const float*)d_in[8];
    const float* qkv_b      = (const float*)d_in[9];
    const float* attn_out_w = (const float*)d_in[10];
    const float* attn_out_b = (const float*)d_in[11];
    const float* ln2_w      = (const float*)d_in[12];
    const float* fc1_w      = (const float*)d_in[13];
    const float* fc1_b      = (const float*)d_in[14];
    const float* fc2_w      = (const float*)d_in[15];
    const float* fc2_b      = (const float*)d_in[16];
    const float* ln_post_w  = (const float*)d_in[17];
    const float* proj_out_w = (const float*)d_in[18];
    const float* proj_out_b = (const float*)d_in[19];
    float* out = (float*)d_out;

    float* patch = SC + OFF_PATCH;
    float* x     = SC + OFF_X;
    float* h     = SC + OFF_H;
    float* qkv   = SC + OFF_QKV;
    float* Qp    = SC + OFF_Q;
    float* Kp    = SC + OFF_K;
    float* Vt    = SC + OFF_V;
    float* att   = SC + OFF_ATT;
    float* mlp   = SC + OFF_MLP;
    float* cosb  = SC + OFF_COS;
    float* sinb  = SC + OFF_SIN;

    // Weights are fed RAW to the tf32 MMA (hardware truncation) — no tfround.
    patchify_kernel<<<(Bv*NPATCH*PATCH_F + 255)/256, 256>>>(videos, patch);
    rope_cs_kernel<<<Sv, 32>>>(cosb, sinb);
    mma_gemm<64,64,0><<<dim3(WIDTH/64, P_ROWS/64), 128, GEMM_SMEM_64>>>(
        patch, proj_in_w, proj_in_b, nullptr, h, P_ROWS, WIDTH, PATCH_F);
    build_x_kernel<<<M_ROWS, 128>>>(h, mask_token, ln_pre_t_w, ln_pre_p_w, x);

    for (int l = 0; l < LAYERS; l++) {
        const float* l1w  = ln1_w      + (size_t)l * WIDTH;
        const float* qw   = qkv_w      + (size_t)l * 3*WIDTH*WIDTH;
        const float* qb   = qkv_b      + (size_t)l * 3*WIDTH;
        const float* aow  = attn_out_w + (size_t)l * WIDTH*WIDTH;
        const float* aob  = attn_out_b + (size_t)l * WIDTH;
        const float* l2w  = ln2_w      + (size_t)l * WIDTH;
        const float* f1w  = fc1_w      + (size_t)l * MLPD*WIDTH;
        const float* f1b  = fc1_b      + (size_t)l * MLPD;
        const float* f2w  = fc2_w      + (size_t)l * WIDTH*MLPD;
        const float* f2b  = fc2_b      + (size_t)l * WIDTH;

        rmsnorm_kernel<<<M_ROWS, 128>>>(x, l1w, h);
        mma_gemm<128,128,0><<<dim3(3*WIDTH/128, M_ROWS/128), 128, GEMM_SMEM_128>>>(
            h, qw, qb, nullptr, qkv, M_ROWS, 3*WIDTH, WIDTH);
        rope_split_kernel<<<M_ROWS, 256>>>(qkv, cosb, sinb, Qp, Kp, Vt);
        flash_kernel<<<dim3(Sv/FQT, BH), FTH, FLASH_SMEM>>>(Qp, Kp, Vt, att);
        mma_gemm<64,64,1><<<dim3(WIDTH/64, M_ROWS/64), 128, GEMM_SMEM_64>>>(
            att, aow, aob, x, x, M_ROWS, WIDTH, WIDTH);
        rmsnorm_kernel<<<M_ROWS, 128>>>(x, l2w, h);
        mma_gemm<128,128,2><<<dim3(MLPD/128, M_ROWS/128), 128, GEMM_SMEM_128>>>(
            h, f1w, f1b, nullptr, mlp, M_ROWS, MLPD, WIDTH);
        mma_gemm<64,64,1><<<dim3(WIDTH/64, M_ROWS/64), 128, GEMM_SMEM_64>>>(
            mlp, f2w, f2b, x, x, M_ROWS, WIDTH, MLPD);
    }

    final_norm_kernel<<<Bv*NTOK, 128>>>(x, ln_post_w, h);
    proj_out_kernel<<<Bv*NTOK, 160>>>(h, proj_out_w, proj_out_b, out);
}